// round 2
// baseline (speedup 1.0000x reference)
#include <cuda_runtime.h>
#include <cstdint>

#define Bn 16
#define Cn 256
#define Ln 4096
#define Pn 100
#define Qn 20
#define TL 64              // l-tile per block
#define SROW 260           // Xs row stride in floats: 1040B rows -> 16B aligned, conflict-free LDS.128
#define NWARP 8
#define PPW 13             // projections per warp (8*13 = 104 >= 100, tail zero-padded)
#define PPAD (NWARP * PPW) // 104

__global__ void zero_cdf_kernel(float* out) {
    int i = blockIdx.x * 256 + threadIdx.x;
    if (i < Bn * Pn * Qn) out[i] = 0.0f;
}

__device__ __forceinline__ unsigned long long ffma2(unsigned long long a,
                                                    unsigned long long b,
                                                    unsigned long long c) {
    unsigned long long d;
    asm("fma.rn.f32x2 %0, %1, %2, %3;" : "=l"(d) : "l"(a), "l"(b), "l"(c));
    return d;
}
__device__ __forceinline__ void unpack2(unsigned long long v, float& x, float& y) {
    asm("mov.b64 {%0,%1}, %2;" : "=f"(x), "=f"(y) : "l"(v));
}

__global__ __launch_bounds__(256, 1)
void csf_main_kernel(const float* __restrict__ X,
                     const float* __restrict__ proj,
                     const float* __restrict__ minv,
                     const float* __restrict__ maxv,
                     float* __restrict__ out) {
    extern __shared__ float sm[];
    float* Xs  = sm;                       // [TL][SROW]
    float* pst = sm + TL * SROW;           // [PPAD][Cn], rows >= Pn are zeros
    float* thr = pst + PPAD * Cn;          // [Pn*Qn]

    const int tid  = threadIdx.x;
    const int w    = tid >> 5;
    const int lane = tid & 31;
    const int b    = blockIdx.x / (Ln / TL);
    const int l0   = (blockIdx.x % (Ln / TL)) * TL;

    // Stage projections once per block (zero-fill padded rows), coalesced float4.
    {
        const int total4 = PPAD * Cn / 4;          // 6656 float4
        const int lim4   = Pn * Cn / 4;            // 6400 real
        for (int i = tid; i < total4; i += 256) {
            float4 v = make_float4(0.f, 0.f, 0.f, 0.f);
            if (i < lim4) v = ((const float4*)proj)[i];
            ((float4*)pst)[i] = v;
        }
    }

    // Thresholds: thr[p][q] = min + (max-min)*(q+1)/(Q+1)  (same fp32 expr as reference)
    for (int i = tid; i < Pn * Qn; i += 256) {
        int p = i / Qn, q = i % Qn;
        float f = (float)(q + 1) / (float)(Qn + 1);
        thr[i] = minv[p] + (maxv[p] - minv[p]) * f;
    }

    // Load X tile transposed: Xs[l][c] = X[b][c][l0+l]. LDG.128 over l, coalesced.
    {
        const float* Xb = X + (size_t)b * Cn * Ln + l0;
        int li = (tid & 15) * 4;       // l base: 0,4,...,60
        int c0 = tid >> 4;             // 0..15
        for (int c = c0; c < Cn; c += 16) {
            float4 v = *(const float4*)(Xb + (size_t)c * Ln + li);
            Xs[(li + 0) * SROW + c] = v.x;
            Xs[(li + 1) * SROW + c] = v.y;
            Xs[(li + 2) * SROW + c] = v.z;
            Xs[(li + 3) * SROW + c] = v.w;
        }
    }
    __syncthreads();

    // ---- Main accumulation: warp w owns projections [w*PPW, w*PPW+PPW) ----
    const int pbase = w * PPW;
    const float* ps = pst + pbase * Cn;
    const float* xa = Xs + lane * SROW;          // l = l0 + lane
    const float* xb = Xs + (lane + 32) * SROW;   // l = l0 + lane + 32

    unsigned long long acc0[PPW], acc1[PPW];
    #pragma unroll
    for (int pp = 0; pp < PPW; pp++) { acc0[pp] = 0ull; acc1[pp] = 0ull; }

    #pragma unroll 4
    for (int c = 0; c < Cn; c += 4) {
        ulonglong2 x0 = *(const ulonglong2*)(xa + c);   // (c,c+1),(c+2,c+3) for l_a
        ulonglong2 x1 = *(const ulonglong2*)(xb + c);   // same for l_b
        #pragma unroll
        for (int pp = 0; pp < PPW; pp++) {
            ulonglong2 pv = *(const ulonglong2*)(ps + pp * Cn + c);  // broadcast
            acc0[pp] = ffma2(pv.x, x0.x, acc0[pp]);
            acc0[pp] = ffma2(pv.y, x0.y, acc0[pp]);
            acc1[pp] = ffma2(pv.x, x1.x, acc1[pp]);
            acc1[pp] = ffma2(pv.y, x1.y, acc1[pp]);
        }
    }

    // ---- Epilogue: thresholds -> set stores + cdf counts ----
    float* cdfb = out + b * (Pn * Qn);
    float* setb = out + Bn * Pn * Qn + (size_t)b * Pn * Qn * Ln;

    #pragma unroll
    for (int pp = 0; pp < PPW; pp++) {
        int p = pbase + pp;
        if (p >= Pn) break;   // uniform within warp (only last warp)
        float e0, o0, e1, o1;
        unpack2(acc0[pp], e0, o0);
        unpack2(acc1[pp], e1, o1);
        float a0 = e0 + o0;   // a for l = l0 + lane
        float a1 = e1 + o1;   // a for l = l0 + lane + 32

        float* dst = setb + (size_t)p * Qn * Ln + l0;
        const float* th = thr + p * Qn;

        #pragma unroll
        for (int qq = 0; qq < Qn; qq += 4) {
            unsigned packed = 0;
            #pragma unroll
            for (int j = 0; j < 4; j++) {
                float t = th[qq + j];
                unsigned s0 = (a0 < t) ? 1u : 0u;
                unsigned s1 = (a1 < t) ? 1u : 0u;
                float* row = dst + (size_t)(qq + j) * Ln;
                row[lane]      = (float)s0;
                row[lane + 32] = (float)s1;
                packed += (s0 + s1) << (8 * j);   // per-byte sum <= 64
            }
            unsigned r = __reduce_add_sync(0xffffffffu, packed);
            if (lane == 0) {
                #pragma unroll
                for (int j = 0; j < 4; j++) {
                    float v = (float)((r >> (8 * j)) & 255u) * (1.0f / 4096.0f);
                    atomicAdd(cdfb + p * Qn + qq + j, v);   // exact dyadic -> deterministic
                }
            }
        }
    }
}

extern "C" void kernel_launch(void* const* d_in, const int* in_sizes, int n_in,
                              void* d_out, int out_size) {
    const float* X    = (const float*)d_in[0];
    const float* proj = (const float*)d_in[1];
    const float* minv = (const float*)d_in[2];
    const float* maxv = (const float*)d_in[3];
    float* out = (float*)d_out;

    zero_cdf_kernel<<<(Bn * Pn * Qn + 255) / 256, 256>>>(out);

    const int smem = (TL * SROW + PPAD * Cn + Pn * Qn) * (int)sizeof(float);
    static int attr_set = 0;
    cudaFuncSetAttribute(csf_main_kernel,
                         cudaFuncAttributeMaxDynamicSharedMemorySize, smem);
    (void)attr_set;
    csf_main_kernel<<<Bn * (Ln / TL), 256, smem>>>(X, proj, minv, maxv, out);
}

// round 3
// speedup vs baseline: 1.1617x; 1.1617x over previous
#include <cuda_runtime.h>
#include <cstdint>

#define Bn 16
#define Cn 256
#define Ln 4096
#define Pn 100
#define Qn 20
#define TL 64              // l-tile per block
#define SROW 260           // 1040B rows: 16B-aligned, conflict-free LDS.128
#define NW 16              // warps per block
#define KP 7               // p per warp: p = w + 16k, k < 7
#define PPAD (NW * KP)     // 112 (rows 100..111 zero)

__global__ void zero_cdf_kernel(float* out) {
    int i = blockIdx.x * 256 + threadIdx.x;
    if (i < Bn * Pn * Qn) out[i] = 0.0f;
}

__device__ __forceinline__ unsigned long long ffma2(unsigned long long a,
                                                    unsigned long long b,
                                                    unsigned long long c) {
    unsigned long long d;
    asm("fma.rn.f32x2 %0, %1, %2, %3;" : "=l"(d) : "l"(a), "l"(b), "l"(c));
    return d;
}
__device__ __forceinline__ void unpack2(unsigned long long v, float& x, float& y) {
    asm("mov.b64 {%0,%1}, %2;" : "=f"(x), "=f"(y) : "l"(v));
}

__global__ __launch_bounds__(512, 1)
void csf_main_kernel(const float* __restrict__ X,
                     const float* __restrict__ proj,
                     const float* __restrict__ minv,
                     const float* __restrict__ maxv,
                     float* __restrict__ out) {
    extern __shared__ float sm[];
    float* Xe  = sm;                          // [32][SROW]  even l
    float* Xo  = sm + 32 * SROW;              // [32][SROW]  odd l
    float* pst = sm + 64 * SROW;              // [PPAD][Cn]  rows >= Pn zero
    float* thr = pst + PPAD * Cn;             // [Pn*Qn]

    const int tid  = threadIdx.x;
    const int w    = tid >> 5;
    const int lane = tid & 31;
    const int b    = blockIdx.x / (Ln / TL);
    const int l0   = (blockIdx.x % (Ln / TL)) * TL;

    // Stage projections (zero-fill pad rows), coalesced float4.
    {
        const int total4 = PPAD * Cn / 4;          // 7168
        const int lim4   = Pn * Cn / 4;            // 6400
        for (int i = tid; i < total4; i += 512) {
            float4 v = make_float4(0.f, 0.f, 0.f, 0.f);
            if (i < lim4) v = ((const float4*)proj)[i];
            ((float4*)pst)[i] = v;
        }
    }

    // Thresholds (same fp32 expression as reference).
    for (int i = tid; i < Pn * Qn; i += 512) {
        int p = i / Qn, q = i % Qn;
        float f = (float)(q + 1) / (float)(Qn + 1);
        thr[i] = minv[p] + (maxv[p] - minv[p]) * f;
    }

    // Stage X tile, split even/odd l: Xe[l/2][c] = X[b][c][l0+l] (l even), Xo odd.
    {
        const float* Xb = X + (size_t)b * Cn * Ln + l0;
        for (int i = tid; i < Cn * TL / 4; i += 512) {
            int c  = i >> 4;            // 16 float4 per c-row
            int l4 = (i & 15) * 4;      // 0,4,...,60
            float4 v = *(const float4*)(Xb + (size_t)c * Ln + l4);
            int r = l4 >> 1;
            Xe[(r + 0) * SROW + c] = v.x;
            Xo[(r + 0) * SROW + c] = v.y;
            Xe[(r + 1) * SROW + c] = v.z;
            Xo[(r + 1) * SROW + c] = v.w;
        }
    }
    __syncthreads();

    // ---- Accumulate: warp w owns p = w + 16k (k < 7); thread owns l = 2*lane, 2*lane+1
    const float* xa = Xe + lane * SROW;   // l = l0 + 2*lane
    const float* xb = Xo + lane * SROW;   // l = l0 + 2*lane + 1

    unsigned long long acc0[KP], acc1[KP];
    #pragma unroll
    for (int k = 0; k < KP; k++) { acc0[k] = 0ull; acc1[k] = 0ull; }

    #pragma unroll 2
    for (int c = 0; c < Cn; c += 4) {
        ulonglong2 x0 = *(const ulonglong2*)(xa + c);
        ulonglong2 x1 = *(const ulonglong2*)(xb + c);
        #pragma unroll
        for (int k = 0; k < KP; k++) {
            const float* ps = pst + (w + 16 * k) * Cn + c;
            ulonglong2 pv = *(const ulonglong2*)ps;   // broadcast
            acc0[k] = ffma2(pv.x, x0.x, acc0[k]);
            acc0[k] = ffma2(pv.y, x0.y, acc0[k]);
            acc1[k] = ffma2(pv.x, x1.x, acc1[k]);
            acc1[k] = ffma2(pv.y, x1.y, acc1[k]);
        }
    }

    // ---- Epilogue ----
    float* cdfb = out + b * (Pn * Qn);
    float* setb = out + Bn * Pn * Qn + (size_t)b * Pn * Qn * Ln;

    #pragma unroll
    for (int k = 0; k < KP; k++) {
        int p = w + 16 * k;
        if (p >= Pn) break;   // uniform within warp
        float e0, o0, e1, o1;
        unpack2(acc0[k], e0, o0);
        unpack2(acc1[k], e1, o1);
        float a0 = e0 + o0;   // l = l0 + 2*lane
        float a1 = e1 + o1;   // l = l0 + 2*lane + 1

        float2* dst = (float2*)(setb + (size_t)p * Qn * Ln + l0) + lane;
        const float* th = thr + p * Qn;

        #pragma unroll
        for (int qq = 0; qq < Qn; qq += 4) {
            unsigned packed = 0;
            #pragma unroll
            for (int j = 0; j < 4; j++) {
                float t = th[qq + j];
                unsigned s0 = (a0 < t) ? 1u : 0u;
                unsigned s1 = (a1 < t) ? 1u : 0u;
                dst[(size_t)(qq + j) * (Ln / 2)] = make_float2((float)s0, (float)s1);
                packed += (s0 + s1) << (8 * j);    // per-byte sum <= 64
            }
            unsigned r = __reduce_add_sync(0xffffffffu, packed);
            if (lane < 4) {
                float v = (float)((r >> (8 * lane)) & 255u) * (1.0f / 4096.0f);
                atomicAdd(cdfb + p * Qn + qq + lane, v);   // exact dyadic
            }
        }
    }
}

extern "C" void kernel_launch(void* const* d_in, const int* in_sizes, int n_in,
                              void* d_out, int out_size) {
    const float* X    = (const float*)d_in[0];
    const float* proj = (const float*)d_in[1];
    const float* minv = (const float*)d_in[2];
    const float* maxv = (const float*)d_in[3];
    float* out = (float*)d_out;

    zero_cdf_kernel<<<(Bn * Pn * Qn + 255) / 256, 256>>>(out);

    const int smem = (64 * SROW + PPAD * Cn + Pn * Qn) * (int)sizeof(float);
    cudaFuncSetAttribute(csf_main_kernel,
                         cudaFuncAttributeMaxDynamicSharedMemorySize, smem);
    csf_main_kernel<<<Bn * (Ln / TL), 512, smem>>>(X, proj, minv, maxv, out);
}

// round 4
// speedup vs baseline: 1.4974x; 1.2890x over previous
#include <cuda_runtime.h>
#include <cstdint>

#define Bn 16
#define Cn 256
#define Ln 4096
#define Pn 100
#define Qn 20
#define TL 64              // l-tile
#define SROW 260           // 1040B rows: 16B-aligned, conflict-free LDS.128
#define NW 16              // warps per block
#define KP 7               // p per warp: p = w + 16k, k < 7
#define PPAD (NW * KP)     // 112 (rows 100..111 zero)
#define NTILES (Bn * (Ln / TL))   // 1024
#define GRID 148           // persistent blocks, 1/SM

__global__ void zero_cdf_kernel(float* out) {
    int i = blockIdx.x * 256 + threadIdx.x;
    if (i < Bn * Pn * Qn) out[i] = 0.0f;
}

__device__ __forceinline__ unsigned long long ffma2(unsigned long long a,
                                                    unsigned long long b,
                                                    unsigned long long c) {
    unsigned long long d;
    asm("fma.rn.f32x2 %0, %1, %2, %3;" : "=l"(d) : "l"(a), "l"(b), "l"(c));
    return d;
}
__device__ __forceinline__ void unpack2(unsigned long long v, float& x, float& y) {
    asm("mov.b64 {%0,%1}, %2;" : "=f"(x), "=f"(y) : "l"(v));
}

__global__ __launch_bounds__(512, 1)
void csf_persistent_kernel(const float* __restrict__ X,
                           const float* __restrict__ proj,
                           const float* __restrict__ minv,
                           const float* __restrict__ maxv,
                           float* __restrict__ out) {
    extern __shared__ float sm[];
    float* Xe  = sm;                          // [32][SROW]  even l
    float* Xo  = sm + 32 * SROW;              // [32][SROW]  odd l
    float* pst = sm + 64 * SROW;              // [PPAD][Cn]  rows >= Pn zero
    float* thr = pst + PPAD * Cn;             // [Pn*Qn]

    const int tid  = threadIdx.x;
    const int w    = tid >> 5;
    const int lane = tid & 31;

    // ---- One-time staging: projections (zero-pad) + thresholds ----
    {
        const int total4 = PPAD * Cn / 4;          // 7168
        const int lim4   = Pn * Cn / 4;            // 6400
        for (int i = tid; i < total4; i += 512) {
            float4 v = make_float4(0.f, 0.f, 0.f, 0.f);
            if (i < lim4) v = ((const float4*)proj)[i];
            ((float4*)pst)[i] = v;
        }
        for (int i = tid; i < Pn * Qn; i += 512) {
            int p = i / Qn, q = i % Qn;
            float f = (float)(q + 1) / (float)(Qn + 1);
            thr[i] = minv[p] + (maxv[p] - minv[p]) * f;
        }
    }

    // Per-thread fixed (c, l4) slots for X tile loads: 8 float4 each.
    const int c_lo = tid >> 4;            // 0..31 (j adds 32 each round)
    const int l4   = (tid & 15) * 4;      // 0,4,...,60
    const int r0   = l4 >> 1;             // even/odd row base

    int t = blockIdx.x;
    if (t >= NTILES) return;

    // Prologue: load first tile directly.
    {
        int b  = t >> 6;
        int l0 = (t & 63) * TL;
        const float* Xb = X + (size_t)b * Cn * Ln + l0;
        #pragma unroll
        for (int j = 0; j < 8; j++) {
            int c = c_lo + 32 * j;
            float4 v = *(const float4*)(Xb + (size_t)c * Ln + l4);
            Xe[(r0 + 0) * SROW + c] = v.x;
            Xo[(r0 + 0) * SROW + c] = v.y;
            Xe[(r0 + 1) * SROW + c] = v.z;
            Xo[(r0 + 1) * SROW + c] = v.w;
        }
    }
    __syncthreads();

    const float* xa = Xe + lane * SROW;   // l = l0 + 2*lane
    const float* xb = Xo + lane * SROW;   // l = l0 + 2*lane + 1

    while (true) {
        const int b  = t >> 6;
        const int l0 = (t & 63) * TL;

        // ---- Compute: warp w owns p = w + 16k (k < 7) ----
        unsigned long long acc0[KP], acc1[KP];
        #pragma unroll
        for (int k = 0; k < KP; k++) { acc0[k] = 0ull; acc1[k] = 0ull; }

        #pragma unroll 2
        for (int c = 0; c < Cn; c += 4) {
            ulonglong2 x0 = *(const ulonglong2*)(xa + c);
            ulonglong2 x1 = *(const ulonglong2*)(xb + c);
            #pragma unroll
            for (int k = 0; k < KP; k++) {
                const float* ps = pst + (w + 16 * k) * Cn + c;
                ulonglong2 pv = *(const ulonglong2*)ps;   // broadcast
                acc0[k] = ffma2(pv.x, x0.x, acc0[k]);
                acc0[k] = ffma2(pv.y, x0.y, acc0[k]);
                acc1[k] = ffma2(pv.x, x1.x, acc1[k]);
                acc1[k] = ffma2(pv.y, x1.y, acc1[k]);
            }
        }

        // ---- Prefetch next tile into registers (latency hidden by epilogue) ----
        const int tn = t + GRID;
        const bool have = (tn < NTILES);
        float4 pf[8];
        if (have) {
            int b2  = tn >> 6;
            int l02 = (tn & 63) * TL;
            const float* Xb2 = X + (size_t)b2 * Cn * Ln + l02;
            #pragma unroll
            for (int j = 0; j < 8; j++) {
                int c = c_lo + 32 * j;
                pf[j] = *(const float4*)(Xb2 + (size_t)c * Ln + l4);
            }
        }

        // ---- Epilogue: set stores + cdf counts ----
        float* cdfb = out + b * (Pn * Qn);
        float* setb = out + Bn * Pn * Qn + (size_t)b * Pn * Qn * Ln;

        #pragma unroll
        for (int k = 0; k < KP; k++) {
            int p = w + 16 * k;
            if (p >= Pn) break;   // uniform within warp
            float e0, o0, e1, o1;
            unpack2(acc0[k], e0, o0);
            unpack2(acc1[k], e1, o1);
            float a0 = e0 + o0;   // l = l0 + 2*lane
            float a1 = e1 + o1;   // l = l0 + 2*lane + 1

            float2* dst = (float2*)(setb + (size_t)p * Qn * Ln + l0) + lane;
            const float* th = thr + p * Qn;

            #pragma unroll
            for (int qq = 0; qq < Qn; qq += 4) {
                unsigned packed = 0;
                #pragma unroll
                for (int j = 0; j < 4; j++) {
                    float tt = th[qq + j];
                    unsigned s0 = (a0 < tt) ? 1u : 0u;
                    unsigned s1 = (a1 < tt) ? 1u : 0u;
                    dst[(size_t)(qq + j) * (Ln / 2)] = make_float2((float)s0, (float)s1);
                    packed += (s0 + s1) << (8 * j);    // per-byte sum <= 64
                }
                unsigned r = __reduce_add_sync(0xffffffffu, packed);
                if (lane < 4) {
                    float v = (float)((r >> (8 * lane)) & 255u) * (1.0f / 4096.0f);
                    atomicAdd(cdfb + p * Qn + qq + lane, v);   // exact dyadic
                }
            }
        }

        if (!have) break;

        __syncthreads();   // all warps done reading Xs
        #pragma unroll
        for (int j = 0; j < 8; j++) {
            int c = c_lo + 32 * j;
            Xe[(r0 + 0) * SROW + c] = pf[j].x;
            Xo[(r0 + 0) * SROW + c] = pf[j].y;
            Xe[(r0 + 1) * SROW + c] = pf[j].z;
            Xo[(r0 + 1) * SROW + c] = pf[j].w;
        }
        __syncthreads();   // Xs ready for next iteration

        t = tn;
    }
}

extern "C" void kernel_launch(void* const* d_in, const int* in_sizes, int n_in,
                              void* d_out, int out_size) {
    const float* X    = (const float*)d_in[0];
    const float* proj = (const float*)d_in[1];
    const float* minv = (const float*)d_in[2];
    const float* maxv = (const float*)d_in[3];
    float* out = (float*)d_out;

    zero_cdf_kernel<<<(Bn * Pn * Qn + 255) / 256, 256>>>(out);

    const int smem = (64 * SROW + PPAD * Cn + Pn * Qn) * (int)sizeof(float);
    cudaFuncSetAttribute(csf_persistent_kernel,
                         cudaFuncAttributeMaxDynamicSharedMemorySize, smem);
    csf_persistent_kernel<<<GRID, 512, smem>>>(X, proj, minv, maxv, out);
}